// round 1
// baseline (speedup 1.0000x reference)
#include <cuda_runtime.h>

// Problem constants
#define B_   32
#define T_   16384
#define H_   64
#define G_   192          // 3*H
#define NTHR 192          // one thread per gate row

typedef unsigned long long u64;

// ---- packed f32x2 helpers (sm_100+; ptxas never emits these from C++) ----
__device__ __forceinline__ u64 pack2(float lo, float hi) {
    u64 r; asm("mov.b64 %0, {%1, %2};" : "=l"(r) : "f"(lo), "f"(hi)); return r;
}
__device__ __forceinline__ void unpack2(u64 v, float& lo, float& hi) {
    asm("mov.b64 {%0, %1}, %2;" : "=f"(lo), "=f"(hi) : "l"(v));
}
__device__ __forceinline__ void fma2(u64& d, u64 a, u64 b) {
    asm("fma.rn.f32x2 %0, %1, %2, %0;" : "+l"(d) : "l"(a), "l"(b));
}
__device__ __forceinline__ void add2(u64& d, u64 a) {
    asm("add.rn.f32x2 %0, %0, %1;" : "+l"(d) : "l"(a));
}

// fast sigmoid / tanh via MUFU-backed __expf (few-ulp accurate, saturates correctly)
__device__ __forceinline__ float sigf(float v) {
    return __fdividef(1.0f, 1.0f + __expf(-v));
}
__device__ __forceinline__ float tanhfast(float v) {
    // tanh(v) = 1 - 2/(exp(2v)+1); exp->inf and exp->0 limits both behave.
    return 1.0f - __fdividef(2.0f, __expf(2.0f * v) + 1.0f);
}

// ============================================================================
// Recurrence kernel: one CTA per batch element.
//   threads 0..191 : thread g computes gh[g] = dot(h, w_hh[g]) + b_hh[g]
//   threads 0..63  : thread j then owns hidden unit j (gates + Euler update)
// h lives in SMEM (broadcast reads); w_hh row g lives in registers (packed).
// ============================================================================
__global__ __launch_bounds__(NTHR, 1) void gru_scan_kernel(
    const float* __restrict__ x,      // [B,T,1]
    const float* __restrict__ w_ih,   // [192,1]
    const float* __restrict__ w_hh,   // [192,64]
    const float* __restrict__ b_ih,   // [192]
    const float* __restrict__ b_hh,   // [192]
    float* __restrict__ states)       // [B,T,64]  (d_out + B*T)
{
    __shared__ __align__(16) float hsf[H_];   // current hidden state (broadcast copy)
    __shared__ float ghs[G_];                 // gh exchange buffer

    const int g = threadIdx.x;
    const int b = blockIdx.x;

    // ---- load this thread's w_hh row as 32 packed f32x2 registers ----
    u64 w2[32];
    {
        const float4* wrow = reinterpret_cast<const float4*>(w_hh + g * H_);
        #pragma unroll
        for (int i = 0; i < 16; i++) {
            float4 v = wrow[i];
            w2[2 * i]     = pack2(v.x, v.y);
            w2[2 * i + 1] = pack2(v.z, v.w);
        }
    }
    const float bhh = b_hh[g];

    // ---- gate-thread parameters (hidden unit j = g, for g < 64) ----
    float wi_r = 0.f, wi_z = 0.f, wi_n = 0.f;
    float bi_r = 0.f, bi_z = 0.f, bi_n = 0.f;
    float h_reg = 0.f;                        // this unit's h, register-resident
    if (g < H_) {
        wi_r = w_ih[g];        wi_z = w_ih[H_ + g];   wi_n = w_ih[2 * H_ + g];
        bi_r = b_ih[g];        bi_z = b_ih[H_ + g];   bi_n = b_ih[2 * H_ + g];
        hsf[g] = 0.f;                          // h0 = 0
    }
    __syncthreads();

    const float* xb = x + (size_t)b * T_;
    float* st = states + (size_t)b * T_ * H_;
    const ulonglong2* hpk = reinterpret_cast<const ulonglong2*>(hsf);

    float x_cur = xb[0];

    for (int t = 0; t < T_; t++) {
        // prefetch next x early; latency hides behind the GEMV
        float x_next = xb[(t + 1 < T_) ? (t + 1) : t];

        // ---- GEMV: gh[g] = b_hh[g] + sum_k h[k] * w_hh[g][k]  (packed f32x2) ----
        u64 a0 = pack2(bhh, 0.f), a1 = pack2(0.f, 0.f);
        u64 a2 = pack2(0.f, 0.f), a3 = pack2(0.f, 0.f);
        #pragma unroll
        for (int i = 0; i < 16; i += 2) {
            ulonglong2 hv0 = hpk[i];
            ulonglong2 hv1 = hpk[i + 1];
            fma2(a0, hv0.x, w2[2 * i]);
            fma2(a1, hv0.y, w2[2 * i + 1]);
            fma2(a2, hv1.x, w2[2 * i + 2]);
            fma2(a3, hv1.y, w2[2 * i + 3]);
        }
        add2(a0, a2);
        add2(a1, a3);
        add2(a0, a1);
        float lo, hi; unpack2(a0, lo, hi);
        ghs[g] = lo + hi;

        __syncthreads();   // ghs visible; also protects hsf from early overwrite

        // ---- gates + Euler update (threads 0..63) ----
        if (g < H_) {
            float ghr = ghs[g];
            float ghz = ghs[H_ + g];
            float ghn = ghs[2 * H_ + g];
            float r = sigf(fmaf(x_cur, wi_r, bi_r) + ghr);
            float z = sigf(fmaf(x_cur, wi_z, bi_z) + ghz);
            float n = tanhfast(fmaf(x_cur, wi_n, bi_n) + r * ghn);
            // h_new = h + 0.5*(h_cell - h) = 0.5*((1+z)*h + (1-z)*n)
            float hnew = 0.5f * ((1.0f + z) * h_reg + (1.0f - z) * n);
            h_reg = hnew;
            hsf[g] = hnew;
            st[(size_t)t * H_ + g] = hnew;     // states output (off critical path)
        }
        x_cur = x_next;

        __syncthreads();   // hsf updated before next GEMV reads it
    }
}

// ============================================================================
// Output projection: out[b,t] = states[b,t,:] . w_out + b_out + x[b,t]
// Memory-bound; one warp per row, grid-stride.
// ============================================================================
__global__ __launch_bounds__(256) void out_proj_kernel(
    const float* __restrict__ states,  // [B*T, 64]
    const float* __restrict__ x,       // [B*T]
    const float* __restrict__ w_out,   // [64]
    const float* __restrict__ b_out,   // [1]
    float* __restrict__ out)           // [B*T]
{
    const int lane  = threadIdx.x & 31;
    const int warp  = (blockIdx.x * blockDim.x + threadIdx.x) >> 5;
    const int nwarp = (gridDim.x * blockDim.x) >> 5;

    const float w0 = w_out[lane];
    const float w1 = w_out[32 + lane];
    const float bo = b_out[0];

    for (int row = warp; row < B_ * T_; row += nwarp) {
        const float* s = states + (size_t)row * H_;
        float v = fmaf(s[lane], w0, s[lane + 32] * w1);
        #pragma unroll
        for (int o = 16; o > 0; o >>= 1)
            v += __shfl_xor_sync(0xFFFFFFFFu, v, o);
        if (lane == 0) out[row] = v + bo + x[row];
    }
}

// ============================================================================
// Launch: d_out = [ out (B*T floats) | states (B*T*H floats) ]
// ============================================================================
extern "C" void kernel_launch(void* const* d_in, const int* in_sizes, int n_in,
                              void* d_out, int out_size)
{
    const float* x     = (const float*)d_in[0];
    const float* w_ih  = (const float*)d_in[1];
    const float* w_hh  = (const float*)d_in[2];
    const float* b_ih  = (const float*)d_in[3];
    const float* b_hh  = (const float*)d_in[4];
    const float* w_out = (const float*)d_in[5];
    const float* b_out = (const float*)d_in[6];

    float* out    = (float*)d_out;
    float* states = out + (size_t)B_ * T_;

    gru_scan_kernel<<<B_, NTHR>>>(x, w_ih, w_hh, b_ih, b_hh, states);
    out_proj_kernel<<<296, 256>>>(states, x, w_out, b_out, out);
}

// round 2
// speedup vs baseline: 1.3931x; 1.3931x over previous
#include <cuda_runtime.h>

// Problem constants
#define B_   32
#define T_   16384
#define H_   64
#define NTHR 128          // 4 warps: thread = (unit, K-half)

typedef unsigned long long u64;

#define NLOG2E  (-1.4426950408889634f)   // -log2(e)
#define P2LOG2E ( 2.8853900817779268f)   //  2*log2(e)

// ---- packed f32x2 helpers ----
__device__ __forceinline__ u64 pack2(float lo, float hi) {
    u64 r; asm("mov.b64 %0, {%1, %2};" : "=l"(r) : "f"(lo), "f"(hi)); return r;
}
__device__ __forceinline__ void unpack2(u64 v, float& lo, float& hi) {
    asm("mov.b64 {%0, %1}, %2;" : "=f"(lo), "=f"(hi) : "l"(v));
}
__device__ __forceinline__ void fma2(u64& d, u64 a, u64 b) {
    asm("fma.rn.f32x2 %0, %1, %2, %0;" : "+l"(d) : "l"(a), "l"(b));
}
__device__ __forceinline__ void add2(u64& d, u64 a) {
    asm("add.rn.f32x2 %0, %0, %1;" : "+l"(d) : "l"(a));
}
__device__ __forceinline__ float ex2f(float v) {
    float r; asm("ex2.approx.f32 %0, %1;" : "=f"(r) : "f"(v)); return r;
}
__device__ __forceinline__ float rcpf(float v) {
    float r; asm("rcp.approx.f32 %0, %1;" : "=f"(r) : "f"(v)); return r;
}

// ============================================================================
// Recurrence: one CTA (128 threads) per batch element.
//   unit = wid*16 + (lane&15)  in [0,64)
//   half = lane>>4             K-half of the dot
// Each thread: 3 gate dots (r,z,n) for its unit over 32 of 64 h-elements
// (48 FFMA2, weights register-resident). Partner combine via shfl_xor(16).
// Both halves redundantly compute gates -> no gh exchange, ONE bar per step.
// h double-buffered in SMEM.
// ============================================================================
__global__ __launch_bounds__(NTHR, 1) void gru_scan_kernel(
    const float* __restrict__ x,      // [B,T,1]
    const float* __restrict__ w_ih,   // [192,1]
    const float* __restrict__ w_hh,   // [192,64]
    const float* __restrict__ b_ih,   // [192]
    const float* __restrict__ b_hh,   // [192]
    float* __restrict__ states)       // [B,T,64]
{
    __shared__ __align__(16) float hbuf[2][H_];

    const int tid  = threadIdx.x;
    const int wid  = tid >> 5;
    const int lane = tid & 31;
    const int unit = wid * 16 + (lane & 15);
    const int half = lane >> 4;
    const int b    = blockIdx.x;

    // ---- register-resident weights: rows unit, 64+unit, 128+unit; K-half ----
    u64 wr[16], wz[16], wn[16];
    {
        const float4* pr = reinterpret_cast<const float4*>(w_hh + (unit        ) * H_ + half * 32);
        const float4* pz = reinterpret_cast<const float4*>(w_hh + (unit +   H_ ) * H_ + half * 32);
        const float4* pn = reinterpret_cast<const float4*>(w_hh + (unit + 2*H_ ) * H_ + half * 32);
        #pragma unroll
        for (int i = 0; i < 8; i++) {
            float4 a = pr[i]; wr[2*i] = pack2(a.x, a.y); wr[2*i+1] = pack2(a.z, a.w);
            float4 c = pz[i]; wz[2*i] = pack2(c.x, c.y); wz[2*i+1] = pack2(c.z, c.w);
            float4 d = pn[i]; wn[2*i] = pack2(d.x, d.y); wn[2*i+1] = pack2(d.z, d.w);
        }
    }

    // ---- per-unit scalar constants, pre-scaled by log2e factors ----
    const float wirs = NLOG2E  * w_ih[unit];
    const float wizs = NLOG2E  * w_ih[H_ + unit];
    const float wins = P2LOG2E * w_ih[2*H_ + unit];
    const float crs  = NLOG2E  * (b_ih[unit]        + b_hh[unit]);
    const float czs  = NLOG2E  * (b_ih[H_ + unit]   + b_hh[H_ + unit]);
    const float bins = P2LOG2E *  b_ih[2*H_ + unit];
    const float bhn2 = P2LOG2E *  b_hh[2*H_ + unit];

    if (tid < H_) hbuf[0][tid] = 0.0f;   // h0 = 0
    __syncthreads();

    const float* xb = x + (size_t)b * T_;
    float* st = states + (size_t)b * T_ * H_;

    float h_reg = 0.0f;     // this unit's h (tracked identically in both halves)
    float x_cur = xb[0];

    for (int t = 0; t < T_; t++) {
        const int p = t & 1;
        float x_next = xb[(t + 1 < T_) ? (t + 1) : t];

        // input-side pre-activations (off the critical chain)
        const float pre_r = fmaf(x_cur, wirs, crs);
        const float pre_z = fmaf(x_cur, wizs, czs);
        const float in2   = fmaf(x_cur, wins, bins);

        // ---- load h half: 32 floats = 16 u64 (8 x LDS.128, broadcast) ----
        const ulonglong2* hp =
            reinterpret_cast<const ulonglong2*>(&hbuf[p][half * 32]);
        u64 h2[16];
        #pragma unroll
        for (int i = 0; i < 8; i++) {
            ulonglong2 v = hp[i];
            h2[2*i] = v.x; h2[2*i+1] = v.y;
        }

        // ---- 3 half-dots: 48 FFMA2, 2 accumulators per gate ----
        u64 ar0 = pack2(0.f,0.f), ar1 = pack2(0.f,0.f);
        u64 az0 = pack2(0.f,0.f), az1 = pack2(0.f,0.f);
        u64 an0 = pack2(0.f,0.f), an1 = pack2(0.f,0.f);
        #pragma unroll
        for (int i = 0; i < 16; i += 2) {
            fma2(ar0, h2[i],   wr[i]);   fma2(ar1, h2[i+1], wr[i+1]);
            fma2(az0, h2[i],   wz[i]);   fma2(az1, h2[i+1], wz[i+1]);
            fma2(an0, h2[i],   wn[i]);   fma2(an1, h2[i+1], wn[i+1]);
        }
        add2(ar0, ar1); add2(az0, az1); add2(an0, an1);
        float rl, rh, zl, zh, nl, nh;
        unpack2(ar0, rl, rh); unpack2(az0, zl, zh); unpack2(an0, nl, nh);
        float dr = rl + rh, dz = zl + zh, dn = nl + nh;

        // combine K-halves (partner = lane ^ 16, same warp)
        dr += __shfl_xor_sync(0xFFFFFFFFu, dr, 16);
        dz += __shfl_xor_sync(0xFFFFFFFFu, dz, 16);
        dn += __shfl_xor_sync(0xFFFFFFFFu, dn, 16);

        // ---- gates (redundant in both halves; ex2/rcp chains) ----
        float er   = ex2f(fmaf(dr, NLOG2E, pre_r));
        float ez   = ex2f(fmaf(dz, NLOG2E, pre_z));
        float ghn2 = fmaf(dn, P2LOG2E, bhn2);
        float r    = rcpf(1.0f + er);
        float zs   = rcpf(1.0f + ez);
        float En   = ex2f(fmaf(r, ghn2, in2));
        float rn   = rcpf(1.0f + En);
        // hnew = 0.5(1+z)h + 0.5(1-z)n,  n = 1 - 2*rn
        float A    = fmaf(0.5f, zs, 0.5f);
        float base = fmaf(A, h_reg, fmaf(-0.5f, zs, 0.5f));
        float hnew = fmaf(zs - 1.0f, rn, base);

        h_reg = hnew;
        if (half == 0) {
            hbuf[p ^ 1][unit] = hnew;
            st[(size_t)t * H_ + unit] = hnew;   // off critical path
        }
        x_cur = x_next;

        __syncthreads();   // single bar: publishes hbuf[p^1] for next step
    }
}

// ============================================================================
// Output projection: out[b,t] = states[b,t,:] . w_out + b_out + x[b,t]
// float2 loads, one warp per row, full-occupancy grid.
// ============================================================================
__global__ __launch_bounds__(256) void out_proj_kernel(
    const float* __restrict__ states,  // [B*T, 64]
    const float* __restrict__ x,       // [B*T]
    const float* __restrict__ w_out,   // [64]
    const float* __restrict__ b_out,   // [1]
    float* __restrict__ out)           // [B*T]
{
    const int lane  = threadIdx.x & 31;
    const int warp  = (blockIdx.x * blockDim.x + threadIdx.x) >> 5;
    const int nwarp = (gridDim.x * blockDim.x) >> 5;

    const float2 w = reinterpret_cast<const float2*>(w_out)[lane];
    const float bo = b_out[0];

    for (int row = warp; row < B_ * T_; row += nwarp) {
        const float2 s = reinterpret_cast<const float2*>(states + (size_t)row * H_)[lane];
        float v = fmaf(s.x, w.x, s.y * w.y);
        #pragma unroll
        for (int o = 16; o > 0; o >>= 1)
            v += __shfl_xor_sync(0xFFFFFFFFu, v, o);
        if (lane == 0) out[row] = v + bo + x[row];
    }
}

// ============================================================================
// Launch: d_out = [ out (B*T floats) | states (B*T*H floats) ]
// ============================================================================
extern "C" void kernel_launch(void* const* d_in, const int* in_sizes, int n_in,
                              void* d_out, int out_size)
{
    const float* x     = (const float*)d_in[0];
    const float* w_ih  = (const float*)d_in[1];
    const float* w_hh  = (const float*)d_in[2];
    const float* b_ih  = (const float*)d_in[3];
    const float* b_hh  = (const float*)d_in[4];
    const float* w_out = (const float*)d_in[5];
    const float* b_out = (const float*)d_in[6];

    float* out    = (float*)d_out;
    float* states = out + (size_t)B_ * T_;

    gru_scan_kernel<<<B_, NTHR>>>(x, w_ih, w_hh, b_ih, b_hh, states);
    out_proj_kernel<<<1184, 256>>>(states, x, w_out, b_out, out);
}

// round 3
// speedup vs baseline: 1.9235x; 1.3807x over previous
#include <cuda_runtime.h>

// Problem constants
#define B_   32
#define T_   16384
#define H_   64
#define NTHR 128          // 4 warps: thread = (unit, K-half)

typedef unsigned long long u64;

// ---- packed f32x2 helpers ----
__device__ __forceinline__ u64 pack2(float lo, float hi) {
    u64 r; asm("mov.b64 %0, {%1, %2};" : "=l"(r) : "f"(lo), "f"(hi)); return r;
}
__device__ __forceinline__ void unpack2(u64 v, float& lo, float& hi) {
    asm("mov.b64 {%0, %1}, %2;" : "=f"(lo), "=f"(hi) : "l"(v));
}
__device__ __forceinline__ void fma2(u64& d, u64 a, u64 b) {
    asm("fma.rn.f32x2 %0, %1, %2, %0;" : "+l"(d) : "l"(a), "l"(b));
}
__device__ __forceinline__ void add2(u64& d, u64 a) {
    asm("add.rn.f32x2 %0, %0, %1;" : "+l"(d) : "l"(a));
}
__device__ __forceinline__ float tanhhw(float v) {      // MUFU.TANH, lat 16
    float r; asm("tanh.approx.f32 %0, %1;" : "=f"(r) : "f"(v)); return r;
}

// ============================================================================
// Recurrence: one CTA (128 threads) per batch element.
//   unit = wid*16 + (lane&15), half = lane>>4 (K-half of the dots)
// Gates via HW tanh:  sigma(v) = 0.5 + 0.5*tanh(v/2)
//   tr = tanh(0.5*vr), tz = tanh(0.5*vz)
//   n-arg: i_n + r*(dn+bhn) = inp + hng + tr*hng,  hng = 0.5*(dn+bhn)
//   hnew  = 0.25*((3+tz)*h + (1-tz)*n)
// ============================================================================
__global__ __launch_bounds__(NTHR, 1) void gru_scan_kernel(
    const float* __restrict__ x,      // [B,T,1]
    const float* __restrict__ w_ih,   // [192,1]
    const float* __restrict__ w_hh,   // [192,64]
    const float* __restrict__ b_ih,   // [192]
    const float* __restrict__ b_hh,   // [192]
    float* __restrict__ states)       // [B,T,64]
{
    __shared__ __align__(16) float hbuf[2][H_];

    const int tid  = threadIdx.x;
    const int wid  = tid >> 5;
    const int lane = tid & 31;
    const int unit = wid * 16 + (lane & 15);
    const int half = lane >> 4;
    const int b    = blockIdx.x;

    // ---- register-resident weights: rows unit, 64+unit, 128+unit; K-half ----
    u64 wr[16], wz[16], wn[16];
    {
        const float4* pr = reinterpret_cast<const float4*>(w_hh + (unit        ) * H_ + half * 32);
        const float4* pz = reinterpret_cast<const float4*>(w_hh + (unit +   H_ ) * H_ + half * 32);
        const float4* pn = reinterpret_cast<const float4*>(w_hh + (unit + 2*H_ ) * H_ + half * 32);
        #pragma unroll
        for (int i = 0; i < 8; i++) {
            float4 a = pr[i]; wr[2*i] = pack2(a.x, a.y); wr[2*i+1] = pack2(a.z, a.w);
            float4 c = pz[i]; wz[2*i] = pack2(c.x, c.y); wz[2*i+1] = pack2(c.z, c.w);
            float4 d = pn[i]; wn[2*i] = pack2(d.x, d.y); wn[2*i+1] = pack2(d.z, d.w);
        }
    }

    // ---- per-unit scalar constants (pre-halved for the tanh formulation) ----
    const float wirh = 0.5f * w_ih[unit];             // 0.5*w_ih_r
    const float wizh = 0.5f * w_ih[H_ + unit];        // 0.5*w_ih_z
    const float win  =        w_ih[2*H_ + unit];      // w_ih_n
    const float crh  = 0.5f * (b_ih[unit]      + b_hh[unit]);
    const float czh  = 0.5f * (b_ih[H_ + unit] + b_hh[H_ + unit]);
    const float bin  =        b_ih[2*H_ + unit];
    const float bh2n = 0.5f * b_hh[2*H_ + unit];

    if (tid < H_) hbuf[0][tid] = 0.0f;   // h0 = 0
    __syncthreads();

    const float* xb = x + (size_t)b * T_;
    float* st = states + (size_t)b * T_ * H_ + unit;

    float h_reg = 0.0f;     // this unit's h (tracked identically in both halves)
    float x_cur = xb[0];

    #pragma unroll 2
    for (int t = 0; t < T_; t++) {
        const int p = t & 1;

        // ---- load h half first: 32 floats (8 x LDS.128, broadcast) ----
        const ulonglong2* hp =
            reinterpret_cast<const ulonglong2*>(&hbuf[p][half * 32]);
        u64 h2[16];
        #pragma unroll
        for (int i = 0; i < 8; i++) {
            ulonglong2 v = hp[i];
            h2[2*i] = v.x; h2[2*i+1] = v.y;
        }

        // fill the LDS shadow: x prefetch + input-side pre-activations
        float x_next = xb[(t + 1 < T_) ? (t + 1) : t];
        const float pre_r = fmaf(x_cur, wirh, crh);   // 0.5*(i_r-part)
        const float pre_z = fmaf(x_cur, wizh, czh);   // 0.5*(i_z-part)
        const float inp   = fmaf(x_cur, win,  bin);   // i_n

        // ---- 3 half-dots: 48 FFMA2, 2 accumulators per gate ----
        u64 ar0 = pack2(0.f,0.f), ar1 = pack2(0.f,0.f);
        u64 az0 = pack2(0.f,0.f), az1 = pack2(0.f,0.f);
        u64 an0 = pack2(0.f,0.f), an1 = pack2(0.f,0.f);
        #pragma unroll
        for (int i = 0; i < 16; i += 2) {
            fma2(ar0, h2[i],   wr[i]);   fma2(ar1, h2[i+1], wr[i+1]);
            fma2(az0, h2[i],   wz[i]);   fma2(az1, h2[i+1], wz[i+1]);
            fma2(an0, h2[i],   wn[i]);   fma2(an1, h2[i+1], wn[i+1]);
        }
        add2(ar0, ar1); add2(az0, az1); add2(an0, an1);
        float rl, rh, zl, zh, nl, nh;
        unpack2(ar0, rl, rh); unpack2(az0, zl, zh); unpack2(an0, nl, nh);
        float dr = rl + rh, dz = zl + zh, dn = nl + nh;

        // combine K-halves (partner = lane ^ 16, same warp)
        dr += __shfl_xor_sync(0xFFFFFFFFu, dr, 16);
        dz += __shfl_xor_sync(0xFFFFFFFFu, dz, 16);
        dn += __shfl_xor_sync(0xFFFFFFFFu, dn, 16);

        // ---- gates via HW tanh (redundant in both halves) ----
        float tr  = tanhhw(fmaf(dr, 0.5f, pre_r));        // tanh(vr/2)
        float tz  = tanhhw(fmaf(dz, 0.5f, pre_z));        // tanh(vz/2)
        float hng = fmaf(dn, 0.5f, bh2n);                 // 0.5*(dn+bhn)
        float vn  = fmaf(tr, hng, hng + inp);             // i_n + r*(dn+bhn)
        float n   = tanhhw(vn);
        float a   = fmaf(tz,  0.25f, 0.75f);
        float bb  = fmaf(tz, -0.25f, 0.25f);
        float hnew = fmaf(a, h_reg, bb * n);

        h_reg = hnew;
        if (half == 0) {
            hbuf[p ^ 1][unit] = hnew;
            st[(size_t)t * H_] = hnew;     // off critical path
        }
        x_cur = x_next;

        __syncthreads();   // single bar: publishes hbuf[p^1] for next step
    }
}

// ============================================================================
// Output projection: out[b,t] = states[b,t,:] . w_out + b_out + x[b,t]
// 2 rows per warp per iteration, float4 loads (512B/warp), 4-deep reduce.
// ============================================================================
__global__ __launch_bounds__(256) void out_proj_kernel(
    const float* __restrict__ states,  // [B*T, 64]
    const float* __restrict__ x,       // [B*T]
    const float* __restrict__ w_out,   // [64]
    const float* __restrict__ b_out,   // [1]
    float* __restrict__ out)           // [B*T]
{
    const int lane  = threadIdx.x & 31;
    const int sub   = lane & 15;       // position within row
    const int hr    = lane >> 4;       // which of the 2 rows
    const int warp  = (blockIdx.x * blockDim.x + threadIdx.x) >> 5;
    const int nwarp = (gridDim.x * blockDim.x) >> 5;

    const float4 w = reinterpret_cast<const float4*>(w_out)[sub];
    const float bo = b_out[0];

    const int npairs = (B_ * T_) >> 1;
    for (int pair = warp; pair < npairs; pair += nwarp) {
        const int row = 2 * pair + hr;
        const float4 s = reinterpret_cast<const float4*>(states + (size_t)row * H_)[sub];
        float v = fmaf(s.x, w.x, fmaf(s.y, w.y, fmaf(s.z, w.z, s.w * w.w)));
        #pragma unroll
        for (int o = 8; o > 0; o >>= 1)
            v += __shfl_xor_sync(0xFFFFFFFFu, v, o);
        if (sub == 0) out[row] = v + bo + x[row];
    }
}

// ============================================================================
// Launch: d_out = [ out (B*T floats) | states (B*T*H floats) ]
// ============================================================================
extern "C" void kernel_launch(void* const* d_in, const int* in_sizes, int n_in,
                              void* d_out, int out_size)
{
    const float* x     = (const float*)d_in[0];
    const float* w_ih  = (const float*)d_in[1];
    const float* w_hh  = (const float*)d_in[2];
    const float* b_ih  = (const float*)d_in[3];
    const float* b_hh  = (const float*)d_in[4];
    const float* w_out = (const float*)d_in[5];
    const float* b_out = (const float*)d_in[6];

    float* out    = (float*)d_out;
    float* states = out + (size_t)B_ * T_;

    gru_scan_kernel<<<B_, NTHR>>>(x, w_ih, w_hh, b_ih, b_hh, states);
    out_proj_kernel<<<1184, 256>>>(states, x, w_out, b_out, out);
}

// round 4
// speedup vs baseline: 1.9425x; 1.0099x over previous
#include <cuda_runtime.h>

// Problem constants
#define B_   32
#define T_   16384
#define H_   64
#define NTHR 128          // 4 warps: thread = (unit, K-half)

typedef unsigned long long u64;

// ---- packed f32x2 helpers ----
__device__ __forceinline__ u64 pack2(float lo, float hi) {
    u64 r; asm("mov.b64 %0, {%1, %2};" : "=l"(r) : "f"(lo), "f"(hi)); return r;
}
__device__ __forceinline__ void unpack2(u64 v, float& lo, float& hi) {
    asm("mov.b64 {%0, %1}, %2;" : "=f"(lo), "=f"(hi) : "l"(v));
}
__device__ __forceinline__ void fma2(u64& d, u64 a, u64 b) {
    asm("fma.rn.f32x2 %0, %1, %2, %0;" : "+l"(d) : "l"(a), "l"(b));
}
__device__ __forceinline__ void add2(u64& d, u64 a) {
    asm("add.rn.f32x2 %0, %0, %1;" : "+l"(d) : "l"(a));
}
__device__ __forceinline__ float tanhhw(float v) {      // MUFU.TANH, lat 16
    float r; asm("tanh.approx.f32 %0, %1;" : "=f"(r) : "f"(v)); return r;
}

// ============================================================================
// Recurrence: one CTA (128 threads) per batch element.
//   unit = wid*16 + (lane&15), half = lane>>4 (K-half of the dots)
// Gate math via HW tanh:  sigma(v) = 0.5 + 0.5*tanh(v/2)
// CRITICAL-PATH SCHEDULE: r-dot issues FIRST; its reduce/shfl/tanh chain
// overlaps the n- and z-dot FFMA2 streams. Only the n-gate tail remains
// serial after the GEMV.
// ============================================================================
__global__ __launch_bounds__(NTHR, 1) void gru_scan_kernel(
    const float* __restrict__ x,      // [B,T,1]
    const float* __restrict__ w_ih,   // [192,1]
    const float* __restrict__ w_hh,   // [192,64]
    const float* __restrict__ b_ih,   // [192]
    const float* __restrict__ b_hh,   // [192]
    float* __restrict__ states)       // [B,T,64]
{
    __shared__ __align__(16) float hbuf[2][H_];

    const int tid  = threadIdx.x;
    const int wid  = tid >> 5;
    const int lane = tid & 31;
    const int unit = wid * 16 + (lane & 15);
    const int half = lane >> 4;
    const int b    = blockIdx.x;

    // ---- register-resident weights: rows unit, 64+unit, 128+unit; K-half ----
    u64 wr[16], wz[16], wn[16];
    {
        const float4* pr = reinterpret_cast<const float4*>(w_hh + (unit        ) * H_ + half * 32);
        const float4* pz = reinterpret_cast<const float4*>(w_hh + (unit +   H_ ) * H_ + half * 32);
        const float4* pn = reinterpret_cast<const float4*>(w_hh + (unit + 2*H_ ) * H_ + half * 32);
        #pragma unroll
        for (int i = 0; i < 8; i++) {
            float4 a = pr[i]; wr[2*i] = pack2(a.x, a.y); wr[2*i+1] = pack2(a.z, a.w);
            float4 c = pz[i]; wz[2*i] = pack2(c.x, c.y); wz[2*i+1] = pack2(c.z, c.w);
            float4 d = pn[i]; wn[2*i] = pack2(d.x, d.y); wn[2*i+1] = pack2(d.z, d.w);
        }
    }

    // ---- per-unit scalar constants (pre-halved for the tanh formulation) ----
    const float wirh = 0.5f * w_ih[unit];             // 0.5*w_ih_r
    const float wizh = 0.5f * w_ih[H_ + unit];        // 0.5*w_ih_z
    const float win  =        w_ih[2*H_ + unit];      // w_ih_n
    const float crh  = 0.5f * (b_ih[unit]      + b_hh[unit]);
    const float czh  = 0.5f * (b_ih[H_ + unit] + b_hh[H_ + unit]);
    const float bin  =        b_ih[2*H_ + unit];
    const float bh2n = 0.5f * b_hh[2*H_ + unit];

    if (tid < H_) hbuf[0][tid] = 0.0f;   // h0 = 0
    __syncthreads();

    const float* xb = x + (size_t)b * T_;
    float* st = states + (size_t)b * T_ * H_ + unit;

    float h_reg = 0.0f;     // this unit's h (tracked identically in both halves)
    float x_cur = xb[0];

    #pragma unroll 2
    for (int t = 0; t < T_; t++) {
        const int p = t & 1;

        // ---- load h half first: 32 floats (8 x LDS.128, broadcast) ----
        const ulonglong2* hp =
            reinterpret_cast<const ulonglong2*>(&hbuf[p][half * 32]);
        u64 h2[16];
        #pragma unroll
        for (int i = 0; i < 8; i++) {
            ulonglong2 v = hp[i];
            h2[2*i] = v.x; h2[2*i+1] = v.y;
        }

        // fill the LDS shadow: x prefetch + input-side pre-activations
        float x_next = xb[(t + 1 < T_) ? (t + 1) : t];
        const float pre_r = fmaf(x_cur, wirh, crh);   // 0.5*(i_r-part)
        const float pre_z = fmaf(x_cur, wizh, czh);   // 0.5*(i_z-part)
        const float inp   = fmaf(x_cur, win,  bin);   // i_n

        // ================= r-dot FIRST (16 FFMA2) =================
        u64 ar0 = pack2(0.f,0.f), ar1 = pack2(0.f,0.f);
        #pragma unroll
        for (int i = 0; i < 16; i += 2) {
            fma2(ar0, h2[i], wr[i]);   fma2(ar1, h2[i+1], wr[i+1]);
        }
        // r tail: reduce + shfl + tanh — overlaps the n/z FFMA2 streams below
        add2(ar0, ar1);
        float rl, rh; unpack2(ar0, rl, rh);
        float dr = rl + rh;
        dr += __shfl_xor_sync(0xFFFFFFFFu, dr, 16);
        float tr = tanhhw(fmaf(dr, 0.5f, pre_r));         // tanh(vr/2)

        // ================= n-dot (16 FFMA2) =================
        u64 an0 = pack2(0.f,0.f), an1 = pack2(0.f,0.f);
        #pragma unroll
        for (int i = 0; i < 16; i += 2) {
            fma2(an0, h2[i], wn[i]);   fma2(an1, h2[i+1], wn[i+1]);
        }

        // ================= z-dot (16 FFMA2) =================
        u64 az0 = pack2(0.f,0.f), az1 = pack2(0.f,0.f);
        #pragma unroll
        for (int i = 0; i < 16; i += 2) {
            fma2(az0, h2[i], wz[i]);   fma2(az1, h2[i+1], wz[i+1]);
        }

        // z tail (NOT on the critical path; only needed at the update)
        add2(az0, az1);
        float zl, zh; unpack2(az0, zl, zh);
        float dz = zl + zh;
        dz += __shfl_xor_sync(0xFFFFFFFFu, dz, 16);
        float tz = tanhhw(fmaf(dz, 0.5f, pre_z));         // tanh(vz/2)

        // n tail — the remaining serial chain after the GEMV
        add2(an0, an1);
        float nl, nh; unpack2(an0, nl, nh);
        float dn = nl + nh;
        dn += __shfl_xor_sync(0xFFFFFFFFu, dn, 16);
        float hng = fmaf(dn, 0.5f, bh2n);                 // 0.5*(dn+bhn)
        float vn  = fmaf(tr, hng, hng + inp);             // i_n + r*(dn+bhn)
        float n   = tanhhw(vn);

        // Euler update: hnew = 0.25*((3+tz)*h + (1-tz)*n)
        float a    = fmaf(tz,  0.25f, 0.75f);
        float bb   = fmaf(tz, -0.25f, 0.25f);
        float hnew = fmaf(a, h_reg, bb * n);

        h_reg = hnew;
        if (half == 0) {
            hbuf[p ^ 1][unit] = hnew;
            st[(size_t)t * H_] = hnew;     // off critical path
        }
        x_cur = x_next;

        __syncthreads();   // single bar: publishes hbuf[p^1] for next step
    }
}

// ============================================================================
// Output projection: out[b,t] = states[b,t,:] . w_out + b_out + x[b,t]
// 2 rows per warp per iteration, float4 loads (512B/warp), 4-deep reduce.
// ============================================================================
__global__ __launch_bounds__(256) void out_proj_kernel(
    const float* __restrict__ states,  // [B*T, 64]
    const float* __restrict__ x,       // [B*T]
    const float* __restrict__ w_out,   // [64]
    const float* __restrict__ b_out,   // [1]
    float* __restrict__ out)           // [B*T]
{
    const int lane  = threadIdx.x & 31;
    const int sub   = lane & 15;       // position within row
    const int hr    = lane >> 4;       // which of the 2 rows
    const int warp  = (blockIdx.x * blockDim.x + threadIdx.x) >> 5;
    const int nwarp = (gridDim.x * blockDim.x) >> 5;

    const float4 w = reinterpret_cast<const float4*>(w_out)[sub];
    const float bo = b_out[0];

    const int npairs = (B_ * T_) >> 1;
    for (int pair = warp; pair < npairs; pair += nwarp) {
        const int row = 2 * pair + hr;
        const float4 s = reinterpret_cast<const float4*>(states + (size_t)row * H_)[sub];
        float v = fmaf(s.x, w.x, fmaf(s.y, w.y, fmaf(s.z, w.z, s.w * w.w)));
        #pragma unroll
        for (int o = 8; o > 0; o >>= 1)
            v += __shfl_xor_sync(0xFFFFFFFFu, v, o);
        if (sub == 0) out[row] = v + bo + x[row];
    }
}

// ============================================================================
// Launch: d_out = [ out (B*T floats) | states (B*T*H floats) ]
// ============================================================================
extern "C" void kernel_launch(void* const* d_in, const int* in_sizes, int n_in,
                              void* d_out, int out_size)
{
    const float* x     = (const float*)d_in[0];
    const float* w_ih  = (const float*)d_in[1];
    const float* w_hh  = (const float*)d_in[2];
    const float* b_ih  = (const float*)d_in[3];
    const float* b_hh  = (const float*)d_in[4];
    const float* w_out = (const float*)d_in[5];
    const float* b_out = (const float*)d_in[6];

    float* out    = (float*)d_out;
    float* states = out + (size_t)B_ * T_;

    gru_scan_kernel<<<B_, NTHR>>>(x, w_ih, w_hh, b_ih, b_hh, states);
    out_proj_kernel<<<1184, 256>>>(states, x, w_out, b_out, out);
}